// round 2
// baseline (speedup 1.0000x reference)
#include <cuda_runtime.h>
#include <math.h>

#define BH 512
#define BW 512
#define BB 8
#define MAXT 160
#define TILE 32
#define NBLOCKS ((BW/TILE)*(BH/TILE)*BB)   // 2048

// ---- device scratch (static zero-init; kernel self-cleans for graph replay) ----
__device__ double g_acc[8];          // [cls*4 + {sumNo,cntNo,sumObj,cntObj}] (log2 domain)
__device__ unsigned int g_ticket;    // last-block election counter

// ------------------------------------------------------------------
// Single fused kernel:
//  - per-block target filter (batch match + rotated-AABB tile cull)
//  - per-pixel sigmoid/heatmap + masked softplus loss accumulation
//  - block reduce -> double atomics -> last-block computes scalar loss
// One block = 32x32 tile of one batch image, 256 threads x 4 px.
// ------------------------------------------------------------------
__global__ __launch_bounds__(256)
void fused_kernel(const float* __restrict__ pred,
                  const float* __restrict__ tgt, int nT,
                  float* __restrict__ out) {
    __shared__ float sc[2][6][MAXT];   // [cls][{c,s,x3,x4,y3,y4}][i]
    __shared__ int   nAct[2];
    __shared__ float sred[8][8];

    const int tid = threadIdx.x;
    const int b   = blockIdx.z;
    const int tx  = blockIdx.x * TILE;
    const int ty  = blockIdx.y * TILE;

    // ---- issue pixel loads EARLY (hide DRAM latency behind target prologue) ----
    const int row = tid >> 3;
    const int col = (tid & 7) << 2;
    const int h = ty + row;
    const int w = tx + col;
    const float* basep = pred + ((size_t)b * 2) * (BH * BW) + (size_t)h * BW + w;
    const float4 p0 = *(const float4*)basep;
    const float4 p1 = *(const float4*)(basep + BH * BW);

    if (tid < 2) nAct[tid] = 0;
    __syncthreads();

    // ---- target prologue: filter raw targets for this (batch, tile) ----
    const float gxlo = tx + 0.5f, gxhi = tx + TILE - 0.5f;
    const float gylo = ty + 0.5f, gyhi = ty + TILE - 0.5f;
    for (int i = tid; i < nT; i += 256) {
        const float* t = tgt + i * 7;
        if ((int)t[0] != b) continue;
        int   cls = (int)t[1];
        float cx = t[2] * 0.125f, cy = t[3] * 0.125f;   // /SCALE (exact pow2)
        float ww = t[4] * 0.125f, hh = t[5] * 0.125f;
        float ang = t[6];
        float c = __cosf(ang), s = __sinf(ang);
        float x =  cx * c + cy * s;
        float y = -cx * s + cy * c;
        float X3 = x - hh * 0.5f, X4 = x + hh * 0.5f;
        float Y3 = y - ww * 0.5f, Y4 = y + ww * 0.5f;
        // rotated-coordinate range of this tile vs outer box
        float vxmin = fminf(c * gxlo, c * gxhi) + fminf(s * gylo, s * gyhi);
        float vxmax = fmaxf(c * gxlo, c * gxhi) + fmaxf(s * gylo, s * gyhi);
        float vymin = fminf(-s * gxlo, -s * gxhi) + fminf(c * gylo, c * gyhi);
        float vymax = fmaxf(-s * gxlo, -s * gxhi) + fmaxf(c * gylo, c * gyhi);
        if (vxmax >= X3 - 0.5f && vxmin <= X4 + 0.5f &&
            vymax >= Y3 - 0.5f && vymin <= Y4 + 0.5f) {
            int p = atomicAdd(&nAct[cls], 1);
            sc[cls][0][p] = c;  sc[cls][1][p] = s;
            sc[cls][2][p] = X3; sc[cls][3][p] = X4;
            sc[cls][4][p] = Y3; sc[cls][5][p] = Y4;
        }
    }
    __syncthreads();

    // ---- per-pixel mask evaluation over the (tiny) active lists ----
    const float gy  = h + 0.5f;
    const float gx0 = w + 0.5f;
    float x0[4] = {p0.x, p0.y, p0.z, p0.w};
    float x1[4] = {p1.x, p1.y, p1.z, p1.w};

    bool objF[2][4], outF[2][4];
    #pragma unroll
    for (int c2 = 0; c2 < 2; c2++)
        #pragma unroll
        for (int k = 0; k < 4; k++) { objF[c2][k] = false; outF[c2][k] = false; }

    #pragma unroll
    for (int cls = 0; cls < 2; cls++) {
        int n = nAct[cls];
        for (int j = 0; j < n; j++) {
            float c  = sc[cls][0][j], s  = sc[cls][1][j];
            float X3 = sc[cls][2][j], X4 = sc[cls][3][j];
            float Y3 = sc[cls][4][j], Y4 = sc[cls][5][j];
            float sgy = s * gy, cgy = c * gy;
            #pragma unroll
            for (int k = 0; k < 4; k++) {
                float gx = gx0 + (float)k;
                float vx = fmaf(c, gx, sgy);
                float vy = fmaf(-s, gx, cgy);
                bool in_ = (vx >= X3) & (vx <= X4) & (vy >= Y3) & (vy <= Y4);
                bool ot_ = (vx >= X3 - 0.5f) & (vx <= X4 + 0.5f) &
                           (vy >= Y3 - 0.5f) & (vy <= Y4 + 0.5f);
                objF[cls][k] |= in_;
                outF[cls][k] |= ot_;
            }
        }
    }

    // ---- transcendental core (log2 domain; scale by ln2 at reduction) ----
    // t = 2^(x*log2e);  log2(1+t) = softplus(x)/ln2;  -log(sig(x)) = ln2*log2(1+t) - x
    const float LOG2E = 1.4426950408889634f;
    float accNo[2] = {0.f, 0.f}, cntNo[2] = {0.f, 0.f};
    float accOb[2] = {0.f, 0.f}, cntOb[2] = {0.f, 0.f};
    float hm[4];
    #pragma unroll
    for (int k = 0; k < 4; k++) {
        float t0 = exp2f(x0[k] * LOG2E);
        float t1 = exp2f(x1[k] * LOG2E);
        float L0 = __log2f(1.0f + t0);            // softplus(x0)/ln2
        float L1 = __log2f(1.0f + t1);
        float tm = fmaxf(t0, t1);
        hm[k] = __fdividef(tm, 1.0f + tm);
        if (!outF[0][k]) { accNo[0] += L0;                       cntNo[0] += 1.0f; }
        if ( objF[0][k]) { accOb[0] += L0 - x0[k] * LOG2E;       cntOb[0] += 1.0f; }
        if (!outF[1][k]) { accNo[1] += L1;                       cntNo[1] += 1.0f; }
        if ( objF[1][k]) { accOb[1] += L1 - x1[k] * LOG2E;       cntOb[1] += 1.0f; }
    }
    float* hout = out + 1 + ((size_t)b * BH + h) * BW + w;
    hout[0] = hm[0]; hout[1] = hm[1]; hout[2] = hm[2]; hout[3] = hm[3];

    // ---- block reduction -> global double atomics ----
    const float LN2 = 0.6931471805599453f;
    float vals[8] = {accNo[0] * LN2, cntNo[0], accOb[0] * LN2, cntOb[0],
                     accNo[1] * LN2, cntNo[1], accOb[1] * LN2, cntOb[1]};
    #pragma unroll
    for (int j = 0; j < 8; j++) {
        float v = vals[j];
        #pragma unroll
        for (int off = 16; off; off >>= 1)
            v += __shfl_down_sync(0xffffffffu, v, off);
        if ((tid & 31) == 0) sred[tid >> 5][j] = v;
    }
    __syncthreads();
    if (tid < 8) {
        float ssum = 0.f;
        #pragma unroll
        for (int wv = 0; wv < 8; wv++) ssum += sred[wv][tid];
        atomicAdd(&g_acc[tid], (double)ssum);
        __threadfence();
    }
    __syncthreads();

    // ---- last-block election: compute scalar loss, self-clean for replay ----
    if (tid == 0) {
        unsigned int ticket = atomicAdd(&g_ticket, 1u);
        if (ticket == NBLOCKS - 1) {
            __threadfence();
            double a[8];
            #pragma unroll
            for (int j = 0; j < 8; j++) a[j] = atomicAdd(&g_acc[j], 0.0);
            double loss = 0.0;
            #pragma unroll
            for (int cls = 0; cls < 2; cls++) {
                double sNo = a[cls * 4 + 0], cNo = a[cls * 4 + 1];
                double sOb = a[cls * 4 + 2], cOb = a[cls * 4 + 3];
                if (cOb > 0.0)
                    loss += sOb / fmax(cOb, 1.0) + sNo / fmax(cNo, 1.0);
            }
            out[0] = (float)loss;
            #pragma unroll
            for (int j = 0; j < 8; j++) g_acc[j] = 0.0;
            g_ticket = 0u;
            __threadfence();
        }
    }
}

// ------------------------------------------------------------------
extern "C" void kernel_launch(void* const* d_in, const int* in_sizes, int n_in,
                              void* d_out, int out_size) {
    const float* pred = (const float*)d_in[0];
    const float* tgt  = (const float*)d_in[1];
    int nT = in_sizes[1] / 7;
    float* out = (float*)d_out;

    dim3 grid(BW / TILE, BH / TILE, BB);
    fused_kernel<<<grid, 256>>>(pred, tgt, nT, out);
}

// round 4
// speedup vs baseline: 1.0150x; 1.0150x over previous
#include <cuda_runtime.h>
#include <math.h>

#define BH 512
#define BW 512
#define BB 8
#define MAXT 160
#define TILE 32
#define NBLOCKS ((BW/TILE)*(BH/TILE)*BB)   // 2048

// ---- device scratch (static zero-init; kernel self-cleans for graph replay) ----
__device__ double g_acc[8];          // [cls*4 + {sumNo,cntNo,sumObj,cntObj}]
__device__ unsigned int g_ticket;

// ------------------------------------------------------------------
__global__ __launch_bounds__(256, 6)
void fused_kernel(const float* __restrict__ pred,
                  const float* __restrict__ tgt, int nT,
                  float* __restrict__ out) {
    __shared__ float sc[2][6][MAXT];
    __shared__ int   nAct[2];
    __shared__ float sred[8][8];

    const int tid = threadIdx.x;
    const int b   = blockIdx.z;
    const int tx  = blockIdx.x * TILE;
    const int ty  = blockIdx.y * TILE;

    // ---- early pixel loads (hide latency behind target prologue) ----
    const int row = tid >> 3;
    const int col = (tid & 7) << 2;
    const int h = ty + row;
    const int w = tx + col;
    const float* basep = pred + ((size_t)b * 2) * (BH * BW) + (size_t)h * BW + w;
    const float4 p0 = *(const float4*)basep;
    const float4 p1 = *(const float4*)(basep + BH * BW);

    if (tid < 2) nAct[tid] = 0;
    __syncthreads();

    // ---- target prologue: filter raw targets for this (batch, tile) ----
    const float gxlo = tx + 0.5f, gxhi = tx + TILE - 0.5f;
    const float gylo = ty + 0.5f, gyhi = ty + TILE - 0.5f;
    for (int i = tid; i < nT; i += 256) {
        const float* t = tgt + i * 7;
        if ((int)t[0] != b) continue;
        int   cls = (int)t[1];
        float cx = t[2] * 0.125f, cy = t[3] * 0.125f;
        float ww = t[4] * 0.125f, hh = t[5] * 0.125f;
        float c = __cosf(t[6]), s = __sinf(t[6]);
        float x =  cx * c + cy * s;
        float y = -cx * s + cy * c;
        float X3 = x - hh * 0.5f, X4 = x + hh * 0.5f;
        float Y3 = y - ww * 0.5f, Y4 = y + ww * 0.5f;
        float vxmin = fminf(c * gxlo, c * gxhi) + fminf(s * gylo, s * gyhi);
        float vxmax = fmaxf(c * gxlo, c * gxhi) + fmaxf(s * gylo, s * gyhi);
        float vymin = fminf(-s * gxlo, -s * gxhi) + fminf(c * gylo, c * gyhi);
        float vymax = fmaxf(-s * gxlo, -s * gxhi) + fmaxf(c * gylo, c * gyhi);
        if (vxmax >= X3 - 0.5f && vxmin <= X4 + 0.5f &&
            vymax >= Y3 - 0.5f && vymin <= Y4 + 0.5f) {
            int p = atomicAdd(&nAct[cls], 1);
            sc[cls][0][p] = c;  sc[cls][1][p] = s;
            sc[cls][2][p] = X3; sc[cls][3][p] = X4;
            sc[cls][4][p] = Y3; sc[cls][5][p] = Y4;
        }
    }
    __syncthreads();
    const int n0 = nAct[0], n1 = nAct[1];

    // ---- transcendental core (log2 domain) ----
    const float LOG2E = 1.4426950408889634f;
    const float LN2   = 0.6931471805599453f;
    float xl0[4] = {p0.x * LOG2E, p0.y * LOG2E, p0.z * LOG2E, p0.w * LOG2E};
    float xl1[4] = {p1.x * LOG2E, p1.y * LOG2E, p1.z * LOG2E, p1.w * LOG2E};
    float L0[4], L1[4];
    float* hout = out + 1 + ((size_t)b * BH + h) * BW + w;
    #pragma unroll
    for (int k = 0; k < 4; k++) {
        float t0 = exp2f(xl0[k]);
        float t1 = exp2f(xl1[k]);
        L0[k] = __log2f(1.0f + t0);
        L1[k] = __log2f(1.0f + t1);
        float tm = fmaxf(t0, t1);
        hout[k] = __fdividef(tm, 1.0f + tm);
    }

    const int wid = tid >> 5;
    if ((n0 | n1) == 0) {
        // ======== FAST PATH: no targets touch this tile ========
        float s0 = L0[0] + L0[1] + L0[2] + L0[3];
        float s1 = L1[0] + L1[1] + L1[2] + L1[3];
        #pragma unroll
        for (int off = 16; off; off >>= 1) {
            s0 += __shfl_down_sync(0xffffffffu, s0, off);
            s1 += __shfl_down_sync(0xffffffffu, s1, off);
        }
        if ((tid & 31) == 0) { sred[wid][0] = s0; sred[wid][1] = s1; }
        __syncthreads();
        if (tid < 2) {
            float ssum = 0.f;
            #pragma unroll
            for (int wv = 0; wv < 8; wv++) ssum += sred[wv][tid];
            atomicAdd(&g_acc[tid * 4], (double)(ssum * LN2));   // sumNo cls
            if (tid == 0) {
                atomicAdd(&g_acc[1], (double)(TILE * TILE));    // cntNo0
                atomicAdd(&g_acc[5], (double)(TILE * TILE));    // cntNo1
            }
            __threadfence();
        }
    } else {
        // ======== SLOW PATH: evaluate masks over active lists ========
        const float gy  = h + 0.5f;
        const float gx0 = w + 0.5f;
        unsigned m = 0;   // bits: obj0=k, out0=8+k, obj1=16+k, out1=24+k
        #pragma unroll
        for (int cls = 0; cls < 2; cls++) {
            int n = cls ? n1 : n0;
            int base = cls * 16;
            for (int j = 0; j < n; j++) {
                float c  = sc[cls][0][j], s  = sc[cls][1][j];
                float X3 = sc[cls][2][j], X4 = sc[cls][3][j];
                float Y3 = sc[cls][4][j], Y4 = sc[cls][5][j];
                float sgy = s * gy, cgy = c * gy;
                #pragma unroll
                for (int k = 0; k < 4; k++) {
                    float gx = gx0 + (float)k;
                    float vx = fmaf(c, gx, sgy);
                    float vy = fmaf(-s, gx, cgy);
                    unsigned in_ = (vx >= X3) & (vx <= X4) & (vy >= Y3) & (vy <= Y4);
                    unsigned ot_ = (vx >= X3 - 0.5f) & (vx <= X4 + 0.5f) &
                                   (vy >= Y3 - 0.5f) & (vy <= Y4 + 0.5f);
                    m |= (in_ << (base + k)) | (ot_ << (base + 8 + k));
                }
            }
        }
        float a0 = 0.f, a1 = 0.f, o0 = 0.f, o1 = 0.f;
        unsigned cnts = 0;  // bytes: [cntNo0, cntOb0, cntNo1, cntOb1], per-lane <=4 each
        #pragma unroll
        for (int k = 0; k < 4; k++) {
            unsigned ob0 = (m >> k) & 1u;
            unsigned no0 = ((~m) >> (8 + k)) & 1u;
            unsigned ob1 = (m >> (16 + k)) & 1u;
            unsigned no1 = ((~m) >> (24 + k)) & 1u;
            if (no0) a0 += L0[k];
            if (ob0) o0 += L0[k] - xl0[k];
            if (no1) a1 += L1[k];
            if (ob1) o1 += L1[k] - xl1[k];
            cnts += no0 | (ob0 << 8) | (no1 << 16) | (ob1 << 24);
        }
        #pragma unroll
        for (int off = 16; off; off >>= 1) {
            a0 += __shfl_down_sync(0xffffffffu, a0, off);
            o0 += __shfl_down_sync(0xffffffffu, o0, off);
            a1 += __shfl_down_sync(0xffffffffu, a1, off);
            o1 += __shfl_down_sync(0xffffffffu, o1, off);
            cnts += __shfl_down_sync(0xffffffffu, cnts, off);  // per-warp field <=128, fits
        }
        if ((tid & 31) == 0) {
            sred[wid][0] = a0; sred[wid][1] = o0;
            sred[wid][2] = a1; sred[wid][3] = o1;
            sred[wid][4] = __uint_as_float(cnts);
        }
        __syncthreads();
        if (tid < 4) {
            float ssum = 0.f;
            #pragma unroll
            for (int wv = 0; wv < 8; wv++) ssum += sred[wv][tid];
            // map: 0->acc[0](sumNo0) 1->acc[2](sumOb0) 2->acc[4](sumNo1) 3->acc[6](sumOb1)
            if (ssum != 0.f) atomicAdd(&g_acc[tid * 2], (double)(ssum * LN2));
        } else if (tid == 4) {
            // FIX: unpack per-warp BEFORE summing (block totals exceed 8 bits)
            unsigned cNo0 = 0, cOb0 = 0, cNo1 = 0, cOb1 = 0;
            #pragma unroll
            for (int wv = 0; wv < 8; wv++) {
                unsigned cw = __float_as_uint(sred[wv][4]);
                cNo0 +=  cw        & 0xffu;
                cOb0 += (cw >> 8)  & 0xffu;
                cNo1 += (cw >> 16) & 0xffu;
                cOb1 += (cw >> 24) & 0xffu;
            }
            if (cNo0) atomicAdd(&g_acc[1], (double)cNo0);
            if (cOb0) atomicAdd(&g_acc[3], (double)cOb0);
            if (cNo1) atomicAdd(&g_acc[5], (double)cNo1);
            if (cOb1) atomicAdd(&g_acc[7], (double)cOb1);
        }
        if (tid < 5) __threadfence();
    }
    __syncthreads();

    // ---- last-block election: finalize scalar loss, self-clean ----
    if (tid == 0) {
        unsigned int ticket = atomicAdd(&g_ticket, 1u);
        if (ticket == NBLOCKS - 1) {
            __threadfence();
            double a[8];
            #pragma unroll
            for (int j = 0; j < 8; j++)
                a[j] = *((volatile double*)&g_acc[j]);
            double loss = 0.0;
            #pragma unroll
            for (int cls = 0; cls < 2; cls++) {
                double sNo = a[cls * 4 + 0], cNo = a[cls * 4 + 1];
                double sOb = a[cls * 4 + 2], cOb = a[cls * 4 + 3];
                if (cOb > 0.0)
                    loss += sOb / fmax(cOb, 1.0) + sNo / fmax(cNo, 1.0);
            }
            out[0] = (float)loss;
            #pragma unroll
            for (int j = 0; j < 8; j++) g_acc[j] = 0.0;
            g_ticket = 0u;
            __threadfence();
        }
    }
}

// ------------------------------------------------------------------
extern "C" void kernel_launch(void* const* d_in, const int* in_sizes, int n_in,
                              void* d_out, int out_size) {
    const float* pred = (const float*)d_in[0];
    const float* tgt  = (const float*)d_in[1];
    int nT = in_sizes[1] / 7;
    float* out = (float*)d_out;

    dim3 grid(BW / TILE, BH / TILE, BB);
    fused_kernel<<<grid, 256>>>(pred, tgt, nT, out);
}

// round 5
// speedup vs baseline: 1.1534x; 1.1364x over previous
#include <cuda_runtime.h>
#include <math.h>

#define BH 512
#define BW 512
#define BB 8
#define MAXT 160
#define TILE 64
#define NBLOCKS ((BW/TILE)*(BH/TILE)*BB)   // 512

// ---- device scratch (static zero-init; kernel self-cleans for graph replay) ----
__device__ double g_acc[8];          // [cls*4 + {sumNo,cntNo,sumObj,cntObj}]
__device__ unsigned int g_ticket;

// ------------------------------------------------------------------
// One block = 64x64 tile of one image. 256 threads x 16 px (4 row-passes).
// ------------------------------------------------------------------
__global__ __launch_bounds__(256, 4)
void fused_kernel(const float* __restrict__ pred,
                  const float* __restrict__ tgt, int nT,
                  float* __restrict__ out) {
    __shared__ float sc[2][6][MAXT];
    __shared__ int   nAct[2];
    __shared__ float sred[8][6];

    const int tid = threadIdx.x;
    const int b   = blockIdx.z;
    const int tx  = blockIdx.x * TILE;
    const int ty  = blockIdx.y * TILE;

    // ---- early pixel loads: 4 passes x 2 classes, MLP=8 ----
    const int row = tid >> 4;          // 0..15
    const int col = (tid & 15) << 2;   // 0..60
    const size_t img = (size_t)BH * BW;
    const float* base0 = pred + (size_t)b * 2 * img + (size_t)(ty + row) * BW + (tx + col);
    float4 f0[4], f1[4];
    #pragma unroll
    for (int p = 0; p < 4; p++) {
        f0[p] = *(const float4*)(base0 + (size_t)p * 16 * BW);
        f1[p] = *(const float4*)(base0 + img + (size_t)p * 16 * BW);
    }

    if (tid < 2) nAct[tid] = 0;
    __syncthreads();

    // ---- target prologue: filter raw targets for this (batch, tile) ----
    const float gxlo = tx + 0.5f, gxhi = tx + TILE - 0.5f;
    const float gylo = ty + 0.5f, gyhi = ty + TILE - 0.5f;
    for (int i = tid; i < nT; i += 256) {
        const float* t = tgt + i * 7;
        if ((int)t[0] != b) continue;
        int   cls = (int)t[1];
        float cx = t[2] * 0.125f, cy = t[3] * 0.125f;
        float ww = t[4] * 0.125f, hh = t[5] * 0.125f;
        float c = __cosf(t[6]), s = __sinf(t[6]);
        float x =  cx * c + cy * s;
        float y = -cx * s + cy * c;
        float X3 = x - hh * 0.5f, X4 = x + hh * 0.5f;
        float Y3 = y - ww * 0.5f, Y4 = y + ww * 0.5f;
        float vxmin = fminf(c * gxlo, c * gxhi) + fminf(s * gylo, s * gyhi);
        float vxmax = fmaxf(c * gxlo, c * gxhi) + fmaxf(s * gylo, s * gyhi);
        float vymin = fminf(-s * gxlo, -s * gxhi) + fminf(c * gylo, c * gyhi);
        float vymax = fmaxf(-s * gxlo, -s * gxhi) + fmaxf(c * gylo, c * gyhi);
        if (vxmax >= X3 - 0.5f && vxmin <= X4 + 0.5f &&
            vymax >= Y3 - 0.5f && vymin <= Y4 + 0.5f) {
            int p = atomicAdd(&nAct[cls], 1);
            sc[cls][0][p] = c;  sc[cls][1][p] = s;
            sc[cls][2][p] = X3; sc[cls][3][p] = X4;
            sc[cls][4][p] = Y3; sc[cls][5][p] = Y4;
        }
    }
    __syncthreads();
    const int n0 = nAct[0], n1 = nAct[1];

    const float LOG2E = 1.4426950408889634f;
    const float LN2   = 0.6931471805599453f;
    const float gx0   = tx + col + 0.5f;
    float* hout = out + 1 + (size_t)b * img + (size_t)(ty + row) * BW + (tx + col);

    float a0 = 0.f, o0 = 0.f, a1 = 0.f, o1 = 0.f;
    unsigned nc, oc;   // 16-bit fields: [cntNoX_cls0 | cls1<<16], per-lane <=16

    if ((n0 | n1) == 0) {
        // ======== FAST PATH: all 4096 px are noobj for both classes ========
        #pragma unroll
        for (int p = 0; p < 4; p++) {
            float xl0[4] = {f0[p].x * LOG2E, f0[p].y * LOG2E, f0[p].z * LOG2E, f0[p].w * LOG2E};
            float xl1[4] = {f1[p].x * LOG2E, f1[p].y * LOG2E, f1[p].z * LOG2E, f1[p].w * LOG2E};
            float* hp = hout + (size_t)p * 16 * BW;
            #pragma unroll
            for (int k = 0; k < 4; k++) {
                float t0 = exp2f(xl0[k]);
                float t1 = exp2f(xl1[k]);
                a0 += __log2f(1.0f + t0);
                a1 += __log2f(1.0f + t1);
                float tm = fmaxf(t0, t1);
                hp[k] = __fdividef(tm, 1.0f + tm);
            }
        }
        nc = 16u | (16u << 16);
        oc = 0u;
    } else {
        // ======== SLOW PATH: per-pass mask evaluation ========
        nc = 0u; oc = 0u;
        #pragma unroll
        for (int p = 0; p < 4; p++) {
            const float gy = ty + p * 16 + row + 0.5f;
            unsigned m0 = 0, m1 = 0;   // bits: obj=k, out=4+k
            for (int j = 0; j < n0; j++) {
                float c  = sc[0][0][j], s  = sc[0][1][j];
                float X3 = sc[0][2][j], X4 = sc[0][3][j];
                float Y3 = sc[0][4][j], Y4 = sc[0][5][j];
                float sgy = s * gy, cgy = c * gy;
                #pragma unroll
                for (int k = 0; k < 4; k++) {
                    float gx = gx0 + (float)k;
                    float vx = fmaf(c, gx, sgy);
                    float vy = fmaf(-s, gx, cgy);
                    unsigned in_ = (vx >= X3) & (vx <= X4) & (vy >= Y3) & (vy <= Y4);
                    unsigned ot_ = (vx >= X3 - 0.5f) & (vx <= X4 + 0.5f) &
                                   (vy >= Y3 - 0.5f) & (vy <= Y4 + 0.5f);
                    m0 |= (in_ << k) | (ot_ << (4 + k));
                }
            }
            for (int j = 0; j < n1; j++) {
                float c  = sc[1][0][j], s  = sc[1][1][j];
                float X3 = sc[1][2][j], X4 = sc[1][3][j];
                float Y3 = sc[1][4][j], Y4 = sc[1][5][j];
                float sgy = s * gy, cgy = c * gy;
                #pragma unroll
                for (int k = 0; k < 4; k++) {
                    float gx = gx0 + (float)k;
                    float vx = fmaf(c, gx, sgy);
                    float vy = fmaf(-s, gx, cgy);
                    unsigned in_ = (vx >= X3) & (vx <= X4) & (vy >= Y3) & (vy <= Y4);
                    unsigned ot_ = (vx >= X3 - 0.5f) & (vx <= X4 + 0.5f) &
                                   (vy >= Y3 - 0.5f) & (vy <= Y4 + 0.5f);
                    m1 |= (in_ << k) | (ot_ << (4 + k));
                }
            }
            float xl0[4] = {f0[p].x * LOG2E, f0[p].y * LOG2E, f0[p].z * LOG2E, f0[p].w * LOG2E};
            float xl1[4] = {f1[p].x * LOG2E, f1[p].y * LOG2E, f1[p].z * LOG2E, f1[p].w * LOG2E};
            float* hp = hout + (size_t)p * 16 * BW;
            #pragma unroll
            for (int k = 0; k < 4; k++) {
                float t0 = exp2f(xl0[k]);
                float t1 = exp2f(xl1[k]);
                float L0 = __log2f(1.0f + t0);
                float L1 = __log2f(1.0f + t1);
                float tm = fmaxf(t0, t1);
                hp[k] = __fdividef(tm, 1.0f + tm);
                unsigned ob0 =  (m0 >> k) & 1u;
                unsigned no0 = ((~m0) >> (4 + k)) & 1u;
                unsigned ob1 =  (m1 >> k) & 1u;
                unsigned no1 = ((~m1) >> (4 + k)) & 1u;
                if (no0) a0 += L0;
                if (ob0) o0 += L0 - xl0[k];
                if (no1) a1 += L1;
                if (ob1) o1 += L1 - xl1[k];
                nc += no0 | (no1 << 16);
                oc += ob0 | (ob1 << 16);
            }
        }
    }

    // ---- block reduction: 4 float sums + 2 packed counts ----
    #pragma unroll
    for (int off = 16; off; off >>= 1) {
        a0 += __shfl_down_sync(0xffffffffu, a0, off);
        o0 += __shfl_down_sync(0xffffffffu, o0, off);
        a1 += __shfl_down_sync(0xffffffffu, a1, off);
        o1 += __shfl_down_sync(0xffffffffu, o1, off);
        nc += __shfl_down_sync(0xffffffffu, nc, off);  // per-warp field <=512, fits 16b
        oc += __shfl_down_sync(0xffffffffu, oc, off);
    }
    const int wid = tid >> 5;
    if ((tid & 31) == 0) {
        sred[wid][0] = a0; sred[wid][1] = o0;
        sred[wid][2] = a1; sred[wid][3] = o1;
        sred[wid][4] = __uint_as_float(nc);
        sred[wid][5] = __uint_as_float(oc);
    }
    __syncthreads();
    if (tid < 4) {
        float ssum = 0.f;
        #pragma unroll
        for (int wv = 0; wv < 8; wv++) ssum += sred[wv][tid];
        // 0->sumNo0(g_acc[0]) 1->sumOb0(g_acc[2]) 2->sumNo1(g_acc[4]) 3->sumOb1(g_acc[6])
        if (ssum != 0.f) atomicAdd(&g_acc[tid * 2], (double)(ssum * LN2));
    } else if (tid == 4) {
        unsigned cNo0 = 0, cNo1 = 0;
        #pragma unroll
        for (int wv = 0; wv < 8; wv++) {
            unsigned cw = __float_as_uint(sred[wv][4]);
            cNo0 += cw & 0xffffu; cNo1 += cw >> 16;
        }
        if (cNo0) atomicAdd(&g_acc[1], (double)cNo0);
        if (cNo1) atomicAdd(&g_acc[5], (double)cNo1);
    } else if (tid == 5) {
        unsigned cOb0 = 0, cOb1 = 0;
        #pragma unroll
        for (int wv = 0; wv < 8; wv++) {
            unsigned cw = __float_as_uint(sred[wv][5]);
            cOb0 += cw & 0xffffu; cOb1 += cw >> 16;
        }
        if (cOb0) atomicAdd(&g_acc[3], (double)cOb0);
        if (cOb1) atomicAdd(&g_acc[7], (double)cOb1);
    }
    if (tid < 6) __threadfence();
    __syncthreads();

    // ---- last-block election: finalize scalar loss, self-clean ----
    if (tid == 0) {
        unsigned int ticket = atomicAdd(&g_ticket, 1u);
        if (ticket == NBLOCKS - 1) {
            __threadfence();
            double a[8];
            #pragma unroll
            for (int j = 0; j < 8; j++)
                a[j] = *((volatile double*)&g_acc[j]);
            double loss = 0.0;
            #pragma unroll
            for (int cls = 0; cls < 2; cls++) {
                double sNo = a[cls * 4 + 0], cNo = a[cls * 4 + 1];
                double sOb = a[cls * 4 + 2], cOb = a[cls * 4 + 3];
                if (cOb > 0.0)
                    loss += sOb / fmax(cOb, 1.0) + sNo / fmax(cNo, 1.0);
            }
            out[0] = (float)loss;
            #pragma unroll
            for (int j = 0; j < 8; j++) g_acc[j] = 0.0;
            g_ticket = 0u;
            __threadfence();
        }
    }
}

// ------------------------------------------------------------------
extern "C" void kernel_launch(void* const* d_in, const int* in_sizes, int n_in,
                              void* d_out, int out_size) {
    const float* pred = (const float*)d_in[0];
    const float* tgt  = (const float*)d_in[1];
    int nT = in_sizes[1] / 7;
    float* out = (float*)d_out;

    dim3 grid(BW / TILE, BH / TILE, BB);
    fused_kernel<<<grid, 256>>>(pred, tgt, nT, out);
}